// round 2
// baseline (speedup 1.0000x reference)
#include <cuda_runtime.h>
#include <cstdint>

// MessagePassing: out[src[e], k] += edge_attrs_flat[k*E + e]
// edge_attrs: float32 [E*F]  (logically (E,F), values consumed as (F,E))
// attr_idx:   [2*E] ints (row 0 = src) — dtype int32 (JAX x64 off) or int64; detected at runtime
// out:        float32 [N*F]

static constexpr int F = 16;

__device__ int g_idx_is64;   // 1 if indices are int64, 0 if int32

// Detect index width: under int64 little-endian, odd int32 positions are the
// high words of values < 2^32 -> all zero. Random int32 indices in [0,100000)
// are zero with p=1e-5; 128 simultaneous zeros from int32 data ~ impossible.
__global__ void detect_idx_kernel(const int* __restrict__ idx32, int n32) {
    if (threadIdx.x == 0 && blockIdx.x == 0) {
        int all_zero = 1;
        int samples = 128;
        int stride = (n32 / 2) / samples;   // in int64 element units
        if (stride < 1) stride = 1;
        for (int j = 0; j < samples; j++) {
            long long p = 2LL * (long long)j * stride + 1;  // high word position
            if (p < n32 && idx32[p] != 0) { all_zero = 0; break; }
        }
        g_idx_is64 = all_zero;
    }
}

__global__ void zero_out_kernel(float4* __restrict__ out4, int n4) {
    int i = blockIdx.x * blockDim.x + threadIdx.x;
    if (i < n4) out4[i] = make_float4(0.f, 0.f, 0.f, 0.f);
}

__global__ void __launch_bounds__(256)
scatter_kernel(const float* __restrict__ attrs,
               const void* __restrict__ src_idx,
               float* __restrict__ out,
               int E) {
    int e = blockIdx.x * blockDim.x + threadIdx.x;
    if (e >= E) return;

    int src;
    if (g_idx_is64) {
        src = (int)((const long long*)src_idx)[e];
    } else {
        src = ((const int*)src_idx)[e];
    }

    float v[F];
#pragma unroll
    for (int k = 0; k < F; k++) {
        v[k] = attrs[(size_t)k * (size_t)E + (size_t)e];
    }

    float* dst = out + (size_t)src * F;
#pragma unroll
    for (int k = 0; k < F; k += 4) {
        asm volatile(
            "red.global.add.v4.f32 [%0], {%1, %2, %3, %4};"
            :: "l"(dst + k), "f"(v[k]), "f"(v[k + 1]), "f"(v[k + 2]), "f"(v[k + 3])
            : "memory");
    }
}

extern "C" void kernel_launch(void* const* d_in, const int* in_sizes, int n_in,
                              void* d_out, int out_size) {
    const float* attrs = (const float*)d_in[0];
    const void* attr_idx = d_in[1];        // (2, E), row 0 = src
    float* out = (float*)d_out;

    int E = in_sizes[0] / F;
    int n_idx_elems = in_sizes[1];         // 2*E element count (dtype-agnostic)

    detect_idx_kernel<<<1, 32>>>((const int*)attr_idx, n_idx_elems);

    int n4 = out_size / 4;
    zero_out_kernel<<<(n4 + 255) / 256, 256>>>((float4*)out, n4);

    scatter_kernel<<<(E + 255) / 256, 256>>>(attrs, attr_idx, out, E);
}